// round 3
// baseline (speedup 1.0000x reference)
#include <cuda_runtime.h>
#include <cstdint>

#define NP 100000
#define ND 20000
#define DD 128
#define EP 1600000
#define ED 800000

#define BM 64
#define BK 16
#define XPAD 20   // BK + 4 pad: float4-aligned stores, conflict-free broadcast reads

// ---- scratch (device globals; allocation APIs are forbidden) ----
__device__ float g_deg[NP];
__device__ float g_cinv[NP];
__device__ float g_dinv[NP];
__device__ float g_agg[(size_t)NP * DD];   // self-loop + PPI-aggregated x_prot
__device__ float g_dti[(size_t)NP * DD];   // scatter-mean of drug messages (= x2)
__device__ float g_msgs[(size_t)ND * DD];  // x_drug @ W_td + b_td

// ------------------------------------------------------------------
// Small prep kernels
// ------------------------------------------------------------------
__global__ __launch_bounds__(256) void k_init() {
    int i = blockIdx.x * 256 + threadIdx.x;
    if (i < NP) { g_deg[i] = 1.0f; g_cinv[i] = 0.0f; }  // deg starts at 1 (self-loop)
}

__global__ __launch_bounds__(256) void k_deg(const int* __restrict__ col) {
    int e = blockIdx.x * 256 + threadIdx.x;
    if (e < EP) atomicAdd(&g_deg[__ldg(col + e)], 1.0f);
}

__global__ __launch_bounds__(256) void k_cnt(const int* __restrict__ p) {
    int e = blockIdx.x * 256 + threadIdx.x;
    if (e < ED) atomicAdd(&g_cinv[__ldg(p + e)], 1.0f);
}

__global__ __launch_bounds__(256) void k_fin() {
    int i = blockIdx.x * 256 + threadIdx.x;
    if (i < NP) {
        g_dinv[i] = rsqrtf(g_deg[i]);               // deg >= 1 always
        g_cinv[i] = 1.0f / fmaxf(g_cinv[i], 1.0f);  // scatter-mean divisor
    }
}

// init g_agg with self-loop term dinv[i]^2 * x[i], zero g_dti
__global__ __launch_bounds__(256) void k_vinit(const float* __restrict__ x) {
    int idx = blockIdx.x * 256 + threadIdx.x;  // float4 index
    if (idx < NP * (DD / 4)) {
        int r = idx >> 5;   // 32 float4 per row
        float dv = g_dinv[r];
        float s = dv * dv;
        float4 v = ((const float4*)x)[idx];
        v.x *= s; v.y *= s; v.z *= s; v.w *= s;
        ((float4*)g_agg)[idx] = v;
        ((float4*)g_dti)[idx] = make_float4(0.f, 0.f, 0.f, 0.f);
    }
}

// ------------------------------------------------------------------
// Scatter kernels: one warp per edge, float4 per lane, vector red.add
// ------------------------------------------------------------------
__device__ __forceinline__ void red_add_v4(float* p, float4 v) {
    asm volatile("red.global.add.v4.f32 [%0], {%1, %2, %3, %4};"
                 :
                 : "l"(p), "f"(v.x), "f"(v.y), "f"(v.z), "f"(v.w)
                 : "memory");
}

__global__ __launch_bounds__(256) void k_ppi(const int* __restrict__ er,
                                             const int* __restrict__ ec,
                                             const float* __restrict__ x) {
    int e = blockIdx.x * 8 + (threadIdx.x >> 5);
    if (e >= EP) return;
    int lane = threadIdx.x & 31;
    int r = __ldg(er + e), c = __ldg(ec + e);
    float n = __ldg(g_dinv + r) * __ldg(g_dinv + c);
    float4 v = __ldg((const float4*)(x + (size_t)r * DD) + lane);
    v.x *= n; v.y *= n; v.z *= n; v.w *= n;
    red_add_v4(g_agg + (size_t)c * DD + lane * 4, v);
}

__global__ __launch_bounds__(256) void k_dti(const int* __restrict__ ed,
                                             const int* __restrict__ ep) {
    int e = blockIdx.x * 8 + (threadIdx.x >> 5);
    if (e >= ED) return;
    int lane = threadIdx.x & 31;
    int d = __ldg(ed + e), p = __ldg(ep + e);
    float s = __ldg(g_cinv + p);
    float4 v = __ldg((const float4*)(g_msgs + (size_t)d * DD) + lane);
    v.x *= s; v.y *= s; v.z *= s; v.w *= s;
    red_add_v4(g_dti + (size_t)p * DD + lane * 4, v);
}

// ------------------------------------------------------------------
// Drug GEMM: g_msgs = x_drug @ W_td + b_td   (20000 x 128 @ 128 x 128)
// 256 threads, 64-row tile, full 128 cols, thread computes 4x8
// ------------------------------------------------------------------
__global__ __launch_bounds__(256) void k_gemm_drug(
    const float* __restrict__ A, const float* __restrict__ B,
    const float* __restrict__ bias) {
    __shared__ float Xs[BM][XPAD];
    __shared__ float Bs[BK][DD];
    int tid = threadIdx.x;
    int tx = tid & 15, ty = tid >> 4;
    int row0 = blockIdx.x * BM;

    float acc[4][8];
#pragma unroll
    for (int i = 0; i < 4; i++)
#pragma unroll
        for (int j = 0; j < 8; j++) acc[i][j] = 0.f;

    for (int k0 = 0; k0 < DD; k0 += BK) {
        {   // X tile: 64x16 = 256 float4
            int r = tid >> 2;
            int kc = (tid & 3) * 4;
            float4 v = make_float4(0.f, 0.f, 0.f, 0.f);
            int gr = row0 + r;
            if (gr < ND) v = *(const float4*)(A + (size_t)gr * DD + k0 + kc);
            *(float4*)&Xs[r][kc] = v;
        }
#pragma unroll
        for (int u = 0; u < 2; u++) {  // B tile: 16x128 = 512 float4
            int idx = tid + u * 256;
            int k = idx >> 5, c4 = idx & 31;
            *(float4*)&Bs[k][c4 * 4] =
                *(const float4*)(B + (size_t)(k0 + k) * DD + c4 * 4);
        }
        __syncthreads();
#pragma unroll
        for (int k = 0; k < BK; k++) {
            float a[4];
#pragma unroll
            for (int i = 0; i < 4; i++) a[i] = Xs[ty * 4 + i][k];
            float4 b0 = *(const float4*)&Bs[k][tx * 8];
            float4 b1 = *(const float4*)&Bs[k][tx * 8 + 4];
            float b[8] = {b0.x, b0.y, b0.z, b0.w, b1.x, b1.y, b1.z, b1.w};
#pragma unroll
            for (int i = 0; i < 4; i++)
#pragma unroll
                for (int j = 0; j < 8; j++) acc[i][j] += a[i] * b[j];
        }
        __syncthreads();
    }
#pragma unroll
    for (int i = 0; i < 4; i++) {
        int r = row0 + ty * 4 + i;
        if (r < ND) {
#pragma unroll
            for (int j = 0; j < 8; j++) {
                int c = tx * 8 + j;
                g_msgs[(size_t)r * DD + c] = acc[i][j] + __ldg(bias + c);
            }
        }
    }
}

// ------------------------------------------------------------------
// Main fused kernel:
//   y = g_agg @ W_gcn + x_prot @ W_pr + g_dti + (b_gcn + b_pr) + 1e-6
//   out = LayerNorm(y)  -- row reduction via shfl over 16 lanes
// ------------------------------------------------------------------
__global__ __launch_bounds__(256) void k_main(
    const float* __restrict__ Ax,   // x_prot
    const float* __restrict__ Bg,   // W_gcn
    const float* __restrict__ Bx,   // W_pr
    const float* __restrict__ bg, const float* __restrict__ bx,
    float* __restrict__ out) {
    __shared__ float Xs1[BM][XPAD], Xs2[BM][XPAD];
    __shared__ float Bs1[BK][DD], Bs2[BK][DD];
    int tid = threadIdx.x;
    int tx = tid & 15, ty = tid >> 4;
    int row0 = blockIdx.x * BM;

    float acc[4][8];
#pragma unroll
    for (int i = 0; i < 4; i++)
#pragma unroll
        for (int j = 0; j < 8; j++) acc[i][j] = 0.f;

    for (int k0 = 0; k0 < DD; k0 += BK) {
        {
            int r = tid >> 2;
            int kc = (tid & 3) * 4;
            int gr = row0 + r;
            float4 v1 = make_float4(0.f, 0.f, 0.f, 0.f), v2 = v1;
            if (gr < NP) {
                v1 = *(const float4*)(g_agg + (size_t)gr * DD + k0 + kc);
                v2 = *(const float4*)(Ax + (size_t)gr * DD + k0 + kc);
            }
            *(float4*)&Xs1[r][kc] = v1;
            *(float4*)&Xs2[r][kc] = v2;
        }
#pragma unroll
        for (int u = 0; u < 2; u++) {
            int idx = tid + u * 256;
            int k = idx >> 5, c4 = idx & 31;
            *(float4*)&Bs1[k][c4 * 4] =
                *(const float4*)(Bg + (size_t)(k0 + k) * DD + c4 * 4);
            *(float4*)&Bs2[k][c4 * 4] =
                *(const float4*)(Bx + (size_t)(k0 + k) * DD + c4 * 4);
        }
        __syncthreads();
#pragma unroll
        for (int k = 0; k < BK; k++) {
            float a1[4], a2[4];
#pragma unroll
            for (int i = 0; i < 4; i++) {
                a1[i] = Xs1[ty * 4 + i][k];
                a2[i] = Xs2[ty * 4 + i][k];
            }
            float4 g0 = *(const float4*)&Bs1[k][tx * 8];
            float4 g1 = *(const float4*)&Bs1[k][tx * 8 + 4];
            float4 p0 = *(const float4*)&Bs2[k][tx * 8];
            float4 p1 = *(const float4*)&Bs2[k][tx * 8 + 4];
            float bgv[8] = {g0.x, g0.y, g0.z, g0.w, g1.x, g1.y, g1.z, g1.w};
            float bpv[8] = {p0.x, p0.y, p0.z, p0.w, p1.x, p1.y, p1.z, p1.w};
#pragma unroll
            for (int i = 0; i < 4; i++)
#pragma unroll
                for (int j = 0; j < 8; j++) {
                    acc[i][j] += a1[i] * bgv[j];
                    acc[i][j] += a2[i] * bpv[j];
                }
        }
        __syncthreads();
    }

    // bias sums per column (b_gcn / b_pr are zeros in this dataset, add anyway)
    float bsum[8];
#pragma unroll
    for (int j = 0; j < 8; j++) {
        int c = tx * 8 + j;
        bsum[j] = __ldg(bg + c) + __ldg(bx + c);
    }

#pragma unroll
    for (int i = 0; i < 4; i++) {
        int r = row0 + ty * 4 + i;
        bool valid = r < NP;
        float4 d0 = make_float4(0.f, 0.f, 0.f, 0.f), d1 = d0;
        if (valid) {
            d0 = *(const float4*)(g_dti + (size_t)r * DD + tx * 8);
            d1 = *(const float4*)(g_dti + (size_t)r * DD + tx * 8 + 4);
        }
        float dv[8] = {d0.x, d0.y, d0.z, d0.w, d1.x, d1.y, d1.z, d1.w};
        float y[8];
        float s = 0.f;
#pragma unroll
        for (int j = 0; j < 8; j++) {
            y[j] = acc[i][j] + dv[j] + bsum[j] + 1e-6f;
            s += y[j];
        }
        // reduce across the 16 lanes owning this row (offsets < 16 stay in-group)
#pragma unroll
        for (int o = 8; o > 0; o >>= 1) s += __shfl_xor_sync(0xffffffffu, s, o);
        float mu = s * (1.0f / DD);
        float q = 0.f;
#pragma unroll
        for (int j = 0; j < 8; j++) {
            float d = y[j] - mu;
            q += d * d;
        }
#pragma unroll
        for (int o = 8; o > 0; o >>= 1) q += __shfl_xor_sync(0xffffffffu, q, o);
        float inv = rsqrtf(q * (1.0f / DD) + 1e-5f);
        if (valid) {
            float4 o0, o1;
            o0.x = (y[0] - mu) * inv; o0.y = (y[1] - mu) * inv;
            o0.z = (y[2] - mu) * inv; o0.w = (y[3] - mu) * inv;
            o1.x = (y[4] - mu) * inv; o1.y = (y[5] - mu) * inv;
            o1.z = (y[6] - mu) * inv; o1.w = (y[7] - mu) * inv;
            *(float4*)(out + (size_t)r * DD + tx * 8) = o0;
            *(float4*)(out + (size_t)r * DD + tx * 8 + 4) = o1;
        }
    }
}

// ------------------------------------------------------------------
extern "C" void kernel_launch(void* const* d_in, const int* in_sizes, int n_in,
                              void* d_out, int out_size) {
    const float* x_prot = (const float*)d_in[0];
    const float* x_drug = (const float*)d_in[1];
    const float* W_gcn  = (const float*)d_in[2];
    const float* b_gcn  = (const float*)d_in[3];
    const float* W_td   = (const float*)d_in[4];
    const float* b_td   = (const float*)d_in[5];
    const float* W_pr   = (const float*)d_in[6];
    const float* b_pr   = (const float*)d_in[7];
    const int*   ppi    = (const int*)d_in[8];   // [2, EP]: src = ppi, dst = ppi+EP
    const int*   dti_d  = (const int*)d_in[9];
    const int*   dti_p  = (const int*)d_in[10];
    float* out = (float*)d_out;

    k_init<<<(NP + 255) / 256, 256>>>();
    k_deg<<<(EP + 255) / 256, 256>>>(ppi + EP);
    k_cnt<<<(ED + 255) / 256, 256>>>(dti_p);
    k_fin<<<(NP + 255) / 256, 256>>>();
    k_vinit<<<(NP * (DD / 4) + 255) / 256, 256>>>(x_prot);
    k_gemm_drug<<<(ND + BM - 1) / BM, 256>>>(x_drug, W_td, b_td);
    k_ppi<<<(EP + 7) / 8, 256>>>(ppi, ppi + EP, x_prot);
    k_dti<<<(ED + 7) / 8, 256>>>(dti_d, dti_p);
    k_main<<<(NP + BM - 1) / BM, 256>>>(x_prot, W_gcn, W_pr, b_gcn, b_pr, out);
}

// round 4
// speedup vs baseline: 1.3732x; 1.3732x over previous
#include <cuda_runtime.h>
#include <cstdint>

#define NP 100000
#define ND 20000
#define DD 128
#define EP 1600000
#define ED 800000

#define BM 64
#define BK 16
#define NB 391              // (NP+255)/256 scan blocks

typedef unsigned long long u64;

// ---- scratch (device globals; allocation APIs forbidden) ----
__device__ int   g_pcnt[NP];          // ppi in-degree (no self loop)
__device__ int   g_dcnt[NP];          // dti per-prot count
__device__ int   g_pstart[NP + 1];    // CSR row starts (ppi)
__device__ int   g_dstart[NP + 1];    // CSR row starts (dti)
__device__ int   g_pcur[NP];          // fill cursors
__device__ int   g_dcur[NP];
__device__ int   g_pbsum[NB], g_dbsum[NB];   // block sums
__device__ int   g_pboff[NB], g_dboff[NB];   // scanned block offsets
__device__ int   g_plist[EP];         // src per ppi edge, grouped by dst
__device__ int   g_dlist[ED];         // drug per dti edge, grouped by prot
__device__ float g_dinv[NP];
__device__ float g_cinv[NP];
__device__ float g_agg[(size_t)NP * DD];   // x-aggregate (pre W_gcn)
__device__ float g_dti[(size_t)NP * DD];   // scatter-mean of drug msgs
__device__ float g_msgs[(size_t)ND * DD];  // x_drug @ W_td + b_td

// ---- f32x2 packed-FMA helpers (Blackwell PTX only; ptxas never emits) ----
__device__ __forceinline__ u64 pk2(float lo, float hi) {
    u64 r;
    asm("mov.b64 %0, {%1, %2};" : "=l"(r) : "f"(lo), "f"(hi));
    return r;
}
__device__ __forceinline__ void upk2(float& lo, float& hi, u64 v) {
    asm("mov.b64 {%0, %1}, %2;" : "=f"(lo), "=f"(hi) : "l"(v));
}
__device__ __forceinline__ void fma2(u64& acc, u64 a, u64 b) {
    asm("fma.rn.f32x2 %0, %1, %2, %0;" : "+l"(acc) : "l"(a), "l"(b));
}

// ------------------------------------------------------------------
// CSR build: zero -> count -> scan(3) -> fill
// ------------------------------------------------------------------
__global__ __launch_bounds__(256) void k_zero() {
    int i = blockIdx.x * 256 + threadIdx.x;
    if (i < NP) { g_pcnt[i] = 0; g_dcnt[i] = 0; }
}

__global__ __launch_bounds__(256) void k_count_ppi(const int* __restrict__ dst) {
    int e = blockIdx.x * 256 + threadIdx.x;
    if (e < EP) atomicAdd(&g_pcnt[__ldg(dst + e)], 1);
}

__global__ __launch_bounds__(256) void k_count_dti(const int* __restrict__ p) {
    int e = blockIdx.x * 256 + threadIdx.x;
    if (e < ED) atomicAdd(&g_dcnt[__ldg(p + e)], 1);
}

// per-256-block inclusive scan (both arrays), exclusive starts + block totals
__global__ __launch_bounds__(256) void k_scan1() {
    __shared__ int sp[256], sd[256];
    int t = threadIdx.x;
    int i = blockIdx.x * 256 + t;
    int vp = (i < NP) ? g_pcnt[i] : 0;
    int vd = (i < NP) ? g_dcnt[i] : 0;
    sp[t] = vp; sd[t] = vd;
    __syncthreads();
#pragma unroll
    for (int off = 1; off < 256; off <<= 1) {
        int ap = 0, ad = 0;
        if (t >= off) { ap = sp[t - off]; ad = sd[t - off]; }
        __syncthreads();
        sp[t] += ap; sd[t] += ad;
        __syncthreads();
    }
    if (i < NP) { g_pstart[i] = sp[t] - vp; g_dstart[i] = sd[t] - vd; }
    if (t == 255) { g_pbsum[blockIdx.x] = sp[255]; g_dbsum[blockIdx.x] = sd[255]; }
}

// single-block scan of the NB block sums -> exclusive block offsets
__global__ __launch_bounds__(512) void k_scan2() {
    __shared__ int sp[512], sd[512];
    int t = threadIdx.x;
    int vp = (t < NB) ? g_pbsum[t] : 0;
    int vd = (t < NB) ? g_dbsum[t] : 0;
    sp[t] = vp; sd[t] = vd;
    __syncthreads();
#pragma unroll
    for (int off = 1; off < 512; off <<= 1) {
        int ap = 0, ad = 0;
        if (t >= off) { ap = sp[t - off]; ad = sd[t - off]; }
        __syncthreads();
        sp[t] += ap; sd[t] += ad;
        __syncthreads();
    }
    if (t < NB) { g_pboff[t] = sp[t] - vp; g_dboff[t] = sd[t] - vd; }
}

// add block offsets, init cursors, compute dinv/cinv, set totals
__global__ __launch_bounds__(256) void k_scan3() {
    int i = blockIdx.x * 256 + threadIdx.x;
    if (i < NP) {
        int ps = g_pstart[i] + g_pboff[blockIdx.x];
        int ds = g_dstart[i] + g_dboff[blockIdx.x];
        g_pstart[i] = ps; g_pcur[i] = ps;
        g_dstart[i] = ds; g_dcur[i] = ds;
        g_dinv[i] = rsqrtf((float)(g_pcnt[i] + 1));        // +1 self loop
        g_cinv[i] = 1.0f / fmaxf((float)g_dcnt[i], 1.0f);  // mean divisor
    }
    if (i == 0) { g_pstart[NP] = EP; g_dstart[NP] = ED; }
}

__global__ __launch_bounds__(256) void k_fill_ppi(const int* __restrict__ src,
                                                  const int* __restrict__ dst) {
    int e = blockIdx.x * 256 + threadIdx.x;
    if (e < EP) {
        int c = __ldg(dst + e);
        int pos = atomicAdd(&g_pcur[c], 1);
        g_plist[pos] = __ldg(src + e);
    }
}

__global__ __launch_bounds__(256) void k_fill_dti(const int* __restrict__ d,
                                                  const int* __restrict__ p) {
    int e = blockIdx.x * 256 + threadIdx.x;
    if (e < ED) {
        int c = __ldg(p + e);
        int pos = atomicAdd(&g_dcur[c], 1);
        g_dlist[pos] = __ldg(d + e);
    }
}

// ------------------------------------------------------------------
// Gather: one warp per protein row, produces g_agg and g_dti rows.
//   g_agg[c] = dinv[c] * ( dinv[c]*x[c] + sum_r dinv[r]*x[r] )
//   g_dti[c] = cinv[c] * sum_d msgs[d]
// ------------------------------------------------------------------
__global__ __launch_bounds__(256) void k_gather(const float* __restrict__ x) {
    int c = blockIdx.x * 8 + (threadIdx.x >> 5);
    if (c >= NP) return;
    int lane = threadIdx.x & 31;

    float dc = __ldg(g_dinv + c);
    float4 acc = __ldg((const float4*)(x + (size_t)c * DD) + lane);
    acc.x *= dc; acc.y *= dc; acc.z *= dc; acc.w *= dc;   // self-loop term / dc

    int i = __ldg(g_pstart + c), e = __ldg(g_pstart + c + 1);
    for (; i + 1 < e; i += 2) {
        int r0 = __ldg(g_plist + i), r1 = __ldg(g_plist + i + 1);
        float n0 = __ldg(g_dinv + r0), n1 = __ldg(g_dinv + r1);
        float4 v0 = __ldg((const float4*)(x + (size_t)r0 * DD) + lane);
        float4 v1 = __ldg((const float4*)(x + (size_t)r1 * DD) + lane);
        acc.x += n0 * v0.x + n1 * v1.x;
        acc.y += n0 * v0.y + n1 * v1.y;
        acc.z += n0 * v0.z + n1 * v1.z;
        acc.w += n0 * v0.w + n1 * v1.w;
    }
    if (i < e) {
        int r0 = __ldg(g_plist + i);
        float n0 = __ldg(g_dinv + r0);
        float4 v0 = __ldg((const float4*)(x + (size_t)r0 * DD) + lane);
        acc.x += n0 * v0.x; acc.y += n0 * v0.y;
        acc.z += n0 * v0.z; acc.w += n0 * v0.w;
    }
    acc.x *= dc; acc.y *= dc; acc.z *= dc; acc.w *= dc;
    ((float4*)(g_agg + (size_t)c * DD))[lane] = acc;

    // DTI scatter-mean
    float4 accB = make_float4(0.f, 0.f, 0.f, 0.f);
    i = __ldg(g_dstart + c); e = __ldg(g_dstart + c + 1);
    for (; i + 1 < e; i += 2) {
        int d0 = __ldg(g_dlist + i), d1 = __ldg(g_dlist + i + 1);
        float4 v0 = __ldg((const float4*)(g_msgs + (size_t)d0 * DD) + lane);
        float4 v1 = __ldg((const float4*)(g_msgs + (size_t)d1 * DD) + lane);
        accB.x += v0.x + v1.x; accB.y += v0.y + v1.y;
        accB.z += v0.z + v1.z; accB.w += v0.w + v1.w;
    }
    if (i < e) {
        int d0 = __ldg(g_dlist + i);
        float4 v0 = __ldg((const float4*)(g_msgs + (size_t)d0 * DD) + lane);
        accB.x += v0.x; accB.y += v0.y; accB.z += v0.z; accB.w += v0.w;
    }
    float ci = __ldg(g_cinv + c);
    accB.x *= ci; accB.y *= ci; accB.z *= ci; accB.w *= ci;
    ((float4*)(g_dti + (size_t)c * DD))[lane] = accB;
}

// ------------------------------------------------------------------
// Drug GEMM (FFMA2): g_msgs = x_drug @ W_td + b_td
// thread tile 4 rows x 4 col-pairs; XsT transposed for packed A loads
// ------------------------------------------------------------------
__global__ __launch_bounds__(256) void k_gemm_drug(
    const float* __restrict__ A, const float* __restrict__ B,
    const float* __restrict__ bias) {
    __shared__ float XsT[BK][BM + 4];
    __shared__ float Bs[BK][DD];
    int tid = threadIdx.x;
    int tx = tid & 15, ty = tid >> 4;
    int row0 = blockIdx.x * BM;

    u64 acc[4][4];
#pragma unroll
    for (int i = 0; i < 4; i++)
#pragma unroll
        for (int j = 0; j < 4; j++) acc[i][j] = 0ull;

    for (int k0 = 0; k0 < DD; k0 += BK) {
        {   // X tile 64x16, stored transposed
            int r = tid >> 2;
            int kc = (tid & 3) * 4;
            float4 v = make_float4(0.f, 0.f, 0.f, 0.f);
            int gr = row0 + r;
            if (gr < ND) v = *(const float4*)(A + (size_t)gr * DD + k0 + kc);
            XsT[kc + 0][r] = v.x; XsT[kc + 1][r] = v.y;
            XsT[kc + 2][r] = v.z; XsT[kc + 3][r] = v.w;
        }
#pragma unroll
        for (int u = 0; u < 2; u++) {  // B tile 16x128
            int idx = tid + u * 256;
            int k = idx >> 5, c4 = idx & 31;
            *(float4*)&Bs[k][c4 * 4] =
                *(const float4*)(B + (size_t)(k0 + k) * DD + c4 * 4);
        }
        __syncthreads();
#pragma unroll
        for (int k = 0; k < BK; k++) {
            float4 a = *(const float4*)&XsT[k][ty * 4];
            u64 pa[4] = {pk2(a.x, a.x), pk2(a.y, a.y), pk2(a.z, a.z), pk2(a.w, a.w)};
            ulonglong2 b0 = *(const ulonglong2*)&Bs[k][tx * 8];
            ulonglong2 b1 = *(const ulonglong2*)&Bs[k][tx * 8 + 4];
            u64 bp[4] = {b0.x, b0.y, b1.x, b1.y};
#pragma unroll
            for (int i = 0; i < 4; i++)
#pragma unroll
                for (int j = 0; j < 4; j++) fma2(acc[i][j], pa[i], bp[j]);
        }
        __syncthreads();
    }
#pragma unroll
    for (int i = 0; i < 4; i++) {
        int r = row0 + ty * 4 + i;
        if (r < ND) {
#pragma unroll
            for (int j = 0; j < 4; j++) {
                float lo, hi;
                upk2(lo, hi, acc[i][j]);
                int c = tx * 8 + 2 * j;
                g_msgs[(size_t)r * DD + c]     = lo + __ldg(bias + c);
                g_msgs[(size_t)r * DD + c + 1] = hi + __ldg(bias + c + 1);
            }
        }
    }
}

// ------------------------------------------------------------------
// Main fused kernel (FFMA2 dual GEMM + LayerNorm epilogue):
//   y = g_agg @ W_gcn + x_prot @ W_pr + g_dti + (b_gcn + b_pr) + 1e-6
//   out = LayerNorm(y)
// ------------------------------------------------------------------
__global__ __launch_bounds__(256) void k_main(
    const float* __restrict__ Ax,   // x_prot
    const float* __restrict__ Bg,   // W_gcn
    const float* __restrict__ Bx,   // W_pr
    const float* __restrict__ bg, const float* __restrict__ bx,
    float* __restrict__ out) {
    __shared__ float XsT1[BK][BM + 4], XsT2[BK][BM + 4];
    __shared__ float Bs1[BK][DD], Bs2[BK][DD];
    int tid = threadIdx.x;
    int tx = tid & 15, ty = tid >> 4;
    int row0 = blockIdx.x * BM;

    u64 acc[4][4];
#pragma unroll
    for (int i = 0; i < 4; i++)
#pragma unroll
        for (int j = 0; j < 4; j++) acc[i][j] = 0ull;

    for (int k0 = 0; k0 < DD; k0 += BK) {
        {
            int r = tid >> 2;
            int kc = (tid & 3) * 4;
            int gr = row0 + r;
            float4 v1 = make_float4(0.f, 0.f, 0.f, 0.f), v2 = v1;
            if (gr < NP) {
                v1 = *(const float4*)(g_agg + (size_t)gr * DD + k0 + kc);
                v2 = *(const float4*)(Ax + (size_t)gr * DD + k0 + kc);
            }
            XsT1[kc + 0][r] = v1.x; XsT1[kc + 1][r] = v1.y;
            XsT1[kc + 2][r] = v1.z; XsT1[kc + 3][r] = v1.w;
            XsT2[kc + 0][r] = v2.x; XsT2[kc + 1][r] = v2.y;
            XsT2[kc + 2][r] = v2.z; XsT2[kc + 3][r] = v2.w;
        }
#pragma unroll
        for (int u = 0; u < 2; u++) {
            int idx = tid + u * 256;
            int k = idx >> 5, c4 = idx & 31;
            *(float4*)&Bs1[k][c4 * 4] =
                *(const float4*)(Bg + (size_t)(k0 + k) * DD + c4 * 4);
            *(float4*)&Bs2[k][c4 * 4] =
                *(const float4*)(Bx + (size_t)(k0 + k) * DD + c4 * 4);
        }
        __syncthreads();
#pragma unroll
        for (int k = 0; k < BK; k++) {
            float4 a1 = *(const float4*)&XsT1[k][ty * 4];
            float4 a2 = *(const float4*)&XsT2[k][ty * 4];
            u64 pa1[4] = {pk2(a1.x, a1.x), pk2(a1.y, a1.y),
                          pk2(a1.z, a1.z), pk2(a1.w, a1.w)};
            u64 pa2[4] = {pk2(a2.x, a2.x), pk2(a2.y, a2.y),
                          pk2(a2.z, a2.z), pk2(a2.w, a2.w)};
            ulonglong2 g0 = *(const ulonglong2*)&Bs1[k][tx * 8];
            ulonglong2 g1 = *(const ulonglong2*)&Bs1[k][tx * 8 + 4];
            ulonglong2 p0 = *(const ulonglong2*)&Bs2[k][tx * 8];
            ulonglong2 p1 = *(const ulonglong2*)&Bs2[k][tx * 8 + 4];
            u64 bgp[4] = {g0.x, g0.y, g1.x, g1.y};
            u64 bxp[4] = {p0.x, p0.y, p1.x, p1.y};
#pragma unroll
            for (int i = 0; i < 4; i++)
#pragma unroll
                for (int j = 0; j < 4; j++) {
                    fma2(acc[i][j], pa1[i], bgp[j]);
                    fma2(acc[i][j], pa2[i], bxp[j]);
                }
        }
        __syncthreads();
    }

    float bsum[8];
#pragma unroll
    for (int j = 0; j < 8; j++) {
        int c = tx * 8 + j;
        bsum[j] = __ldg(bg + c) + __ldg(bx + c);
    }

#pragma unroll
    for (int i = 0; i < 4; i++) {
        int r = row0 + ty * 4 + i;
        bool valid = r < NP;
        float4 d0 = make_float4(0.f, 0.f, 0.f, 0.f), d1 = d0;
        if (valid) {
            d0 = *(const float4*)(g_dti + (size_t)r * DD + tx * 8);
            d1 = *(const float4*)(g_dti + (size_t)r * DD + tx * 8 + 4);
        }
        float dv[8] = {d0.x, d0.y, d0.z, d0.w, d1.x, d1.y, d1.z, d1.w};
        float y[8];
#pragma unroll
        for (int j = 0; j < 4; j++) upk2(y[2 * j], y[2 * j + 1], acc[i][j]);
        float s = 0.f;
#pragma unroll
        for (int j = 0; j < 8; j++) {
            y[j] += dv[j] + bsum[j] + 1e-6f;
            s += y[j];
        }
#pragma unroll
        for (int o = 8; o > 0; o >>= 1) s += __shfl_xor_sync(0xffffffffu, s, o);
        float mu = s * (1.0f / DD);
        float q = 0.f;
#pragma unroll
        for (int j = 0; j < 8; j++) {
            float d = y[j] - mu;
            q += d * d;
        }
#pragma unroll
        for (int o = 8; o > 0; o >>= 1) q += __shfl_xor_sync(0xffffffffu, q, o);
        float inv = rsqrtf(q * (1.0f / DD) + 1e-5f);
        if (valid) {
            float4 o0, o1;
            o0.x = (y[0] - mu) * inv; o0.y = (y[1] - mu) * inv;
            o0.z = (y[2] - mu) * inv; o0.w = (y[3] - mu) * inv;
            o1.x = (y[4] - mu) * inv; o1.y = (y[5] - mu) * inv;
            o1.z = (y[6] - mu) * inv; o1.w = (y[7] - mu) * inv;
            *(float4*)(out + (size_t)r * DD + tx * 8) = o0;
            *(float4*)(out + (size_t)r * DD + tx * 8 + 4) = o1;
        }
    }
}

// ------------------------------------------------------------------
extern "C" void kernel_launch(void* const* d_in, const int* in_sizes, int n_in,
                              void* d_out, int out_size) {
    const float* x_prot = (const float*)d_in[0];
    const float* x_drug = (const float*)d_in[1];
    const float* W_gcn  = (const float*)d_in[2];
    const float* b_gcn  = (const float*)d_in[3];
    const float* W_td   = (const float*)d_in[4];
    const float* b_td   = (const float*)d_in[5];
    const float* W_pr   = (const float*)d_in[6];
    const float* b_pr   = (const float*)d_in[7];
    const int*   ppi    = (const int*)d_in[8];   // [2, EP]: src = ppi, dst = ppi+EP
    const int*   dti_d  = (const int*)d_in[9];
    const int*   dti_p  = (const int*)d_in[10];
    float* out = (float*)d_out;

    k_zero<<<NB, 256>>>();
    k_count_ppi<<<(EP + 255) / 256, 256>>>(ppi + EP);
    k_count_dti<<<(ED + 255) / 256, 256>>>(dti_p);
    k_scan1<<<NB, 256>>>();
    k_scan2<<<1, 512>>>();
    k_scan3<<<NB, 256>>>();
    k_fill_ppi<<<(EP + 255) / 256, 256>>>(ppi, ppi + EP);
    k_fill_dti<<<(ED + 255) / 256, 256>>>(dti_d, dti_p);
    k_gemm_drug<<<(ND + BM - 1) / BM, 256>>>(x_drug, W_td, b_td);
    k_gather<<<(NP + 7) / 8, 256>>>(x_prot);
    k_main<<<(NP + BM - 1) / BM, 256>>>(x_prot, W_gcn, W_pr, b_gcn, b_pr, out);
}

// round 5
// speedup vs baseline: 1.4288x; 1.0405x over previous
#include <cuda_runtime.h>
#include <cstdint>

#define NP 100000
#define ND 20000
#define DD 128
#define EP 1600000
#define ED 800000

#define BM 64
#define BK 16
#define NB 391              // (NP+255)/256 scan blocks

typedef unsigned long long u64;

// ---- scratch (device globals; allocation APIs forbidden) ----
__device__ int   g_pcnt[NP];          // ppi in-degree (no self loop)
__device__ int   g_dcnt[NP];          // dti per-prot count
__device__ int   g_pstart[NP + 1];    // CSR row starts (ppi)
__device__ int   g_dstart[NP + 1];    // CSR row starts (dti)
__device__ int   g_pcur[NP];          // fill cursors
__device__ int   g_dcur[NP];
__device__ int   g_pbsum[NB], g_dbsum[NB];
__device__ int   g_pboff[NB], g_dboff[NB];
__device__ int   g_plist[EP];         // src per ppi edge, grouped by dst
__device__ int   g_dlist[ED];         // drug per dti edge, grouped by prot
__device__ float g_dinv[NP];
__device__ float g_cinv[NP];
__device__ float g_h1s[(size_t)NP * DD];   // dinv[r] * (x @ W_gcn)[r]
__device__ float g_h3[(size_t)NP * DD];    // x @ W_pr + b_pr + b_gcn + 1e-6
__device__ float g_msgs[(size_t)ND * DD];  // x_drug @ W_td + b_td

// ---- f32x2 packed-FMA helpers ----
__device__ __forceinline__ u64 pk2(float lo, float hi) {
    u64 r;
    asm("mov.b64 %0, {%1, %2};" : "=l"(r) : "f"(lo), "f"(hi));
    return r;
}
__device__ __forceinline__ void upk2(float& lo, float& hi, u64 v) {
    asm("mov.b64 {%0, %1}, %2;" : "=f"(lo), "=f"(hi) : "l"(v));
}
__device__ __forceinline__ void fma2(u64& acc, u64 a, u64 b) {
    asm("fma.rn.f32x2 %0, %1, %2, %0;" : "+l"(acc) : "l"(a), "l"(b));
}

// ------------------------------------------------------------------
// CSR build
// ------------------------------------------------------------------
__global__ __launch_bounds__(256) void k_zero() {
    int i = blockIdx.x * 256 + threadIdx.x;
    if (i < NP) { g_pcnt[i] = 0; g_dcnt[i] = 0; }
}

__global__ __launch_bounds__(256) void k_count(const int* __restrict__ pdst,
                                               const int* __restrict__ dprot) {
    int e = blockIdx.x * 256 + threadIdx.x;
    if (e < EP) atomicAdd(&g_pcnt[__ldg(pdst + e)], 1);
    else if (e < EP + ED) atomicAdd(&g_dcnt[__ldg(dprot + (e - EP))], 1);
}

__global__ __launch_bounds__(256) void k_scan1() {
    __shared__ int sp[256], sd[256];
    int t = threadIdx.x;
    int i = blockIdx.x * 256 + t;
    int vp = (i < NP) ? g_pcnt[i] : 0;
    int vd = (i < NP) ? g_dcnt[i] : 0;
    sp[t] = vp; sd[t] = vd;
    __syncthreads();
#pragma unroll
    for (int off = 1; off < 256; off <<= 1) {
        int ap = 0, ad = 0;
        if (t >= off) { ap = sp[t - off]; ad = sd[t - off]; }
        __syncthreads();
        sp[t] += ap; sd[t] += ad;
        __syncthreads();
    }
    if (i < NP) { g_pstart[i] = sp[t] - vp; g_dstart[i] = sd[t] - vd; }
    if (t == 255) { g_pbsum[blockIdx.x] = sp[255]; g_dbsum[blockIdx.x] = sd[255]; }
}

__global__ __launch_bounds__(512) void k_scan2() {
    __shared__ int sp[512], sd[512];
    int t = threadIdx.x;
    int vp = (t < NB) ? g_pbsum[t] : 0;
    int vd = (t < NB) ? g_dbsum[t] : 0;
    sp[t] = vp; sd[t] = vd;
    __syncthreads();
#pragma unroll
    for (int off = 1; off < 512; off <<= 1) {
        int ap = 0, ad = 0;
        if (t >= off) { ap = sp[t - off]; ad = sd[t - off]; }
        __syncthreads();
        sp[t] += ap; sd[t] += ad;
        __syncthreads();
    }
    if (t < NB) { g_pboff[t] = sp[t] - vp; g_dboff[t] = sd[t] - vd; }
}

__global__ __launch_bounds__(256) void k_scan3() {
    int i = blockIdx.x * 256 + threadIdx.x;
    if (i < NP) {
        int ps = g_pstart[i] + g_pboff[blockIdx.x];
        int ds = g_dstart[i] + g_dboff[blockIdx.x];
        g_pstart[i] = ps; g_pcur[i] = ps;
        g_dstart[i] = ds; g_dcur[i] = ds;
        g_dinv[i] = rsqrtf((float)(g_pcnt[i] + 1));        // +1 self loop
        g_cinv[i] = 1.0f / fmaxf((float)g_dcnt[i], 1.0f);  // mean divisor
    }
    if (i == 0) { g_pstart[NP] = EP; g_dstart[NP] = ED; }
}

__global__ __launch_bounds__(256) void k_fill(const int* __restrict__ psrc,
                                              const int* __restrict__ pdst,
                                              const int* __restrict__ ddrug,
                                              const int* __restrict__ dprot) {
    int e = blockIdx.x * 256 + threadIdx.x;
    if (e < EP) {
        int c = __ldg(pdst + e);
        int pos = atomicAdd(&g_pcur[c], 1);
        g_plist[pos] = __ldg(psrc + e);
    } else if (e < EP + ED) {
        int ee = e - EP;
        int c = __ldg(dprot + ee);
        int pos = atomicAdd(&g_dcur[c], 1);
        g_dlist[pos] = __ldg(ddrug + ee);
    }
}

// ------------------------------------------------------------------
// Drug GEMM (FFMA2): g_msgs = x_drug @ W_td + b_td
// ------------------------------------------------------------------
__global__ __launch_bounds__(256) void k_gemm_drug(
    const float* __restrict__ A, const float* __restrict__ B,
    const float* __restrict__ bias) {
    __shared__ float XsT[BK][BM + 4];
    __shared__ float Bs[BK][DD];
    int tid = threadIdx.x;
    int tx = tid & 15, ty = tid >> 4;
    int row0 = blockIdx.x * BM;

    u64 acc[4][4];
#pragma unroll
    for (int i = 0; i < 4; i++)
#pragma unroll
        for (int j = 0; j < 4; j++) acc[i][j] = 0ull;

    for (int k0 = 0; k0 < DD; k0 += BK) {
        {
            int r = tid >> 2;
            int kc = (tid & 3) * 4;
            float4 v = make_float4(0.f, 0.f, 0.f, 0.f);
            int gr = row0 + r;
            if (gr < ND) v = *(const float4*)(A + (size_t)gr * DD + k0 + kc);
            XsT[kc + 0][r] = v.x; XsT[kc + 1][r] = v.y;
            XsT[kc + 2][r] = v.z; XsT[kc + 3][r] = v.w;
        }
#pragma unroll
        for (int u = 0; u < 2; u++) {
            int idx = tid + u * 256;
            int k = idx >> 5, c4 = idx & 31;
            *(float4*)&Bs[k][c4 * 4] =
                *(const float4*)(B + (size_t)(k0 + k) * DD + c4 * 4);
        }
        __syncthreads();
#pragma unroll
        for (int k = 0; k < BK; k++) {
            float4 a = *(const float4*)&XsT[k][ty * 4];
            u64 pa[4] = {pk2(a.x, a.x), pk2(a.y, a.y), pk2(a.z, a.z), pk2(a.w, a.w)};
            ulonglong2 b0 = *(const ulonglong2*)&Bs[k][tx * 8];
            ulonglong2 b1 = *(const ulonglong2*)&Bs[k][tx * 8 + 4];
            u64 bp[4] = {b0.x, b0.y, b1.x, b1.y};
#pragma unroll
            for (int i = 0; i < 4; i++)
#pragma unroll
                for (int j = 0; j < 4; j++) fma2(acc[i][j], pa[i], bp[j]);
        }
        __syncthreads();
    }
#pragma unroll
    for (int i = 0; i < 4; i++) {
        int r = row0 + ty * 4 + i;
        if (r < ND) {
#pragma unroll
            for (int j = 0; j < 4; j++) {
                float lo, hi;
                upk2(lo, hi, acc[i][j]);
                int c = tx * 8 + 2 * j;
                g_msgs[(size_t)r * DD + c]     = lo + __ldg(bias + c);
                g_msgs[(size_t)r * DD + c + 1] = hi + __ldg(bias + c + 1);
            }
        }
    }
}

// ------------------------------------------------------------------
// Pre-GEMM (FFMA2, single A tile, dual B):
//   g_h1s = dinv .* (x @ W_gcn)
//   g_h3  = x @ W_pr + b_pr + b_gcn + 1e-6
// ------------------------------------------------------------------
__global__ __launch_bounds__(256) void k_pre(
    const float* __restrict__ A,    // x_prot
    const float* __restrict__ Bg,   // W_gcn
    const float* __restrict__ Bx,   // W_pr
    const float* __restrict__ bg, const float* __restrict__ bx) {
    __shared__ float XsT[BK][BM + 4];
    __shared__ float Bs1[BK][DD], Bs2[BK][DD];
    int tid = threadIdx.x;
    int tx = tid & 15, ty = tid >> 4;
    int row0 = blockIdx.x * BM;

    u64 acc1[4][4], acc2[4][4];
#pragma unroll
    for (int i = 0; i < 4; i++)
#pragma unroll
        for (int j = 0; j < 4; j++) { acc1[i][j] = 0ull; acc2[i][j] = 0ull; }

    for (int k0 = 0; k0 < DD; k0 += BK) {
        {
            int r = tid >> 2;
            int kc = (tid & 3) * 4;
            int gr = row0 + r;
            float4 v = make_float4(0.f, 0.f, 0.f, 0.f);
            if (gr < NP) v = *(const float4*)(A + (size_t)gr * DD + k0 + kc);
            XsT[kc + 0][r] = v.x; XsT[kc + 1][r] = v.y;
            XsT[kc + 2][r] = v.z; XsT[kc + 3][r] = v.w;
        }
#pragma unroll
        for (int u = 0; u < 2; u++) {
            int idx = tid + u * 256;
            int k = idx >> 5, c4 = idx & 31;
            *(float4*)&Bs1[k][c4 * 4] =
                *(const float4*)(Bg + (size_t)(k0 + k) * DD + c4 * 4);
            *(float4*)&Bs2[k][c4 * 4] =
                *(const float4*)(Bx + (size_t)(k0 + k) * DD + c4 * 4);
        }
        __syncthreads();
#pragma unroll
        for (int k = 0; k < BK; k++) {
            float4 a = *(const float4*)&XsT[k][ty * 4];
            u64 pa[4] = {pk2(a.x, a.x), pk2(a.y, a.y), pk2(a.z, a.z), pk2(a.w, a.w)};
            ulonglong2 g0 = *(const ulonglong2*)&Bs1[k][tx * 8];
            ulonglong2 g1 = *(const ulonglong2*)&Bs1[k][tx * 8 + 4];
            ulonglong2 p0 = *(const ulonglong2*)&Bs2[k][tx * 8];
            ulonglong2 p1 = *(const ulonglong2*)&Bs2[k][tx * 8 + 4];
            u64 bgp[4] = {g0.x, g0.y, g1.x, g1.y};
            u64 bxp[4] = {p0.x, p0.y, p1.x, p1.y};
#pragma unroll
            for (int i = 0; i < 4; i++)
#pragma unroll
                for (int j = 0; j < 4; j++) {
                    fma2(acc1[i][j], pa[i], bgp[j]);
                    fma2(acc2[i][j], pa[i], bxp[j]);
                }
        }
        __syncthreads();
    }

    float bsum[8];
#pragma unroll
    for (int j = 0; j < 8; j++) {
        int c = tx * 8 + j;
        bsum[j] = __ldg(bg + c) + __ldg(bx + c) + 1e-6f;
    }

#pragma unroll
    for (int i = 0; i < 4; i++) {
        int r = row0 + ty * 4 + i;
        if (r < NP) {
            float dv = __ldg(g_dinv + r);
            float4 h1a, h1b, h3a, h3b;
            float l0, h0, l1, h1, l2, h2, l3, h3v;
            upk2(l0, h0, acc1[i][0]); upk2(l1, h1, acc1[i][1]);
            upk2(l2, h2, acc1[i][2]); upk2(l3, h3v, acc1[i][3]);
            h1a = make_float4(l0 * dv, h0 * dv, l1 * dv, h1 * dv);
            h1b = make_float4(l2 * dv, h2 * dv, l3 * dv, h3v * dv);
            upk2(l0, h0, acc2[i][0]); upk2(l1, h1, acc2[i][1]);
            upk2(l2, h2, acc2[i][2]); upk2(l3, h3v, acc2[i][3]);
            h3a = make_float4(l0 + bsum[0], h0 + bsum[1], l1 + bsum[2], h1 + bsum[3]);
            h3b = make_float4(l2 + bsum[4], h2 + bsum[5], l3 + bsum[6], h3v + bsum[7]);
            *(float4*)(g_h1s + (size_t)r * DD + tx * 8)     = h1a;
            *(float4*)(g_h1s + (size_t)r * DD + tx * 8 + 4) = h1b;
            *(float4*)(g_h3 + (size_t)r * DD + tx * 8)      = h3a;
            *(float4*)(g_h3 + (size_t)r * DD + tx * 8 + 4)  = h3b;
        }
    }
}

// ------------------------------------------------------------------
// Fused gather + LayerNorm: one warp per protein row.
//   y = dinv[c]*(h1s[c] + sum_r h1s[r]) + cinv[c]*sum_d msgs[d] + h3[c]
//   out = LayerNorm(y)   (128 cols = 32 lanes x float4)
// ------------------------------------------------------------------
__global__ __launch_bounds__(256) void k_gather_ln(float* __restrict__ out) {
    int c = blockIdx.x * 8 + (threadIdx.x >> 5);
    if (c >= NP) return;
    int lane = threadIdx.x & 31;

    // PPI aggregate over pre-scaled h1s (self term included)
    float4 acc = __ldg((const float4*)(g_h1s + (size_t)c * DD) + lane);
    int i = __ldg(g_pstart + c), e = __ldg(g_pstart + c + 1);
    for (; i + 3 < e; i += 4) {
        int r0 = __ldg(g_plist + i),     r1 = __ldg(g_plist + i + 1);
        int r2 = __ldg(g_plist + i + 2), r3 = __ldg(g_plist + i + 3);
        float4 v0 = __ldg((const float4*)(g_h1s + (size_t)r0 * DD) + lane);
        float4 v1 = __ldg((const float4*)(g_h1s + (size_t)r1 * DD) + lane);
        float4 v2 = __ldg((const float4*)(g_h1s + (size_t)r2 * DD) + lane);
        float4 v3 = __ldg((const float4*)(g_h1s + (size_t)r3 * DD) + lane);
        acc.x += (v0.x + v1.x) + (v2.x + v3.x);
        acc.y += (v0.y + v1.y) + (v2.y + v3.y);
        acc.z += (v0.z + v1.z) + (v2.z + v3.z);
        acc.w += (v0.w + v1.w) + (v2.w + v3.w);
    }
    for (; i < e; i++) {
        int r0 = __ldg(g_plist + i);
        float4 v0 = __ldg((const float4*)(g_h1s + (size_t)r0 * DD) + lane);
        acc.x += v0.x; acc.y += v0.y; acc.z += v0.z; acc.w += v0.w;
    }

    // DTI aggregate
    float4 accB = make_float4(0.f, 0.f, 0.f, 0.f);
    i = __ldg(g_dstart + c); e = __ldg(g_dstart + c + 1);
    for (; i + 3 < e; i += 4) {
        int d0 = __ldg(g_dlist + i),     d1 = __ldg(g_dlist + i + 1);
        int d2 = __ldg(g_dlist + i + 2), d3 = __ldg(g_dlist + i + 3);
        float4 v0 = __ldg((const float4*)(g_msgs + (size_t)d0 * DD) + lane);
        float4 v1 = __ldg((const float4*)(g_msgs + (size_t)d1 * DD) + lane);
        float4 v2 = __ldg((const float4*)(g_msgs + (size_t)d2 * DD) + lane);
        float4 v3 = __ldg((const float4*)(g_msgs + (size_t)d3 * DD) + lane);
        accB.x += (v0.x + v1.x) + (v2.x + v3.x);
        accB.y += (v0.y + v1.y) + (v2.y + v3.y);
        accB.z += (v0.z + v1.z) + (v2.z + v3.z);
        accB.w += (v0.w + v1.w) + (v2.w + v3.w);
    }
    for (; i < e; i++) {
        int d0 = __ldg(g_dlist + i);
        float4 v0 = __ldg((const float4*)(g_msgs + (size_t)d0 * DD) + lane);
        accB.x += v0.x; accB.y += v0.y; accB.z += v0.z; accB.w += v0.w;
    }

    float dc = __ldg(g_dinv + c);
    float ci = __ldg(g_cinv + c);
    float4 h3 = __ldg((const float4*)(g_h3 + (size_t)c * DD) + lane);
    float4 y;
    y.x = dc * acc.x + ci * accB.x + h3.x;
    y.y = dc * acc.y + ci * accB.y + h3.y;
    y.z = dc * acc.z + ci * accB.z + h3.z;
    y.w = dc * acc.w + ci * accB.w + h3.w;

    // LayerNorm over the 32-lane row
    float s = (y.x + y.y) + (y.z + y.w);
#pragma unroll
    for (int o = 16; o > 0; o >>= 1) s += __shfl_xor_sync(0xffffffffu, s, o);
    float mu = s * (1.0f / DD);
    float dx = y.x - mu, dy = y.y - mu, dz = y.z - mu, dw = y.w - mu;
    float q = (dx * dx + dy * dy) + (dz * dz + dw * dw);
#pragma unroll
    for (int o = 16; o > 0; o >>= 1) q += __shfl_xor_sync(0xffffffffu, q, o);
    float inv = rsqrtf(q * (1.0f / DD) + 1e-5f);
    float4 o4 = make_float4(dx * inv, dy * inv, dz * inv, dw * inv);
    ((float4*)(out + (size_t)c * DD))[lane] = o4;
}

// ------------------------------------------------------------------
extern "C" void kernel_launch(void* const* d_in, const int* in_sizes, int n_in,
                              void* d_out, int out_size) {
    const float* x_prot = (const float*)d_in[0];
    const float* x_drug = (const float*)d_in[1];
    const float* W_gcn  = (const float*)d_in[2];
    const float* b_gcn  = (const float*)d_in[3];
    const float* W_td   = (const float*)d_in[4];
    const float* b_td   = (const float*)d_in[5];
    const float* W_pr   = (const float*)d_in[6];
    const float* b_pr   = (const float*)d_in[7];
    const int*   ppi    = (const int*)d_in[8];   // [2, EP]: src = ppi, dst = ppi+EP
    const int*   dti_d  = (const int*)d_in[9];
    const int*   dti_p  = (const int*)d_in[10];
    float* out = (float*)d_out;

    k_zero<<<NB, 256>>>();
    k_count<<<(EP + ED + 255) / 256, 256>>>(ppi + EP, dti_p);
    k_scan1<<<NB, 256>>>();
    k_scan2<<<1, 512>>>();
    k_scan3<<<NB, 256>>>();
    k_fill<<<(EP + ED + 255) / 256, 256>>>(ppi, ppi + EP, dti_d, dti_p);
    k_gemm_drug<<<(ND + BM - 1) / BM, 256>>>(x_drug, W_td, b_td);
    k_pre<<<(NP + BM - 1) / BM, 256>>>(x_prot, W_gcn, W_pr, b_gcn, b_pr);
    k_gather_ln<<<(NP + 7) / 8, 256>>>(out);
}

// round 6
// speedup vs baseline: 1.5623x; 1.0935x over previous
#include <cuda_runtime.h>
#include <cuda_fp16.h>
#include <cstdint>

#define NP 100000
#define ND 20000
#define DD 128
#define EP 1600000
#define ED 800000

#define BM 64
#define BK 16
#define NB 391              // (NP+255)/256 scan blocks

typedef unsigned long long u64;

// ---- scratch (device globals; allocation APIs forbidden) ----
__device__ int    g_pcnt[NP];
__device__ int    g_dcnt[NP];
__device__ int    g_pstart[NP + 1];
__device__ int    g_dstart[NP + 1];
__device__ int    g_pcur[NP];
__device__ int    g_dcur[NP];
__device__ int    g_pbsum[NB], g_dbsum[NB];
__device__ int    g_pboff[NB], g_dboff[NB];
__device__ int    g_plist[EP];        // src per ppi edge, grouped by dst
__device__ int    g_dlist[ED];        // drug per dti edge, grouped by prot
__device__ float  g_dinv[NP];
__device__ float  g_cinv[NP];
__device__ __half g_h1s[(size_t)NP * DD];   // fp16: dinv[r] * (x @ W_gcn)[r]
__device__ __half g_msgs[(size_t)ND * DD];  // fp16: x_drug @ W_td + b_td
__device__ float  g_h3[(size_t)NP * DD];    // fp32: x @ W_pr + biases + 1e-6

// ---- f32x2 packed-FMA helpers ----
__device__ __forceinline__ u64 pk2(float lo, float hi) {
    u64 r;
    asm("mov.b64 %0, {%1, %2};" : "=l"(r) : "f"(lo), "f"(hi));
    return r;
}
__device__ __forceinline__ void upk2(float& lo, float& hi, u64 v) {
    asm("mov.b64 {%0, %1}, %2;" : "=f"(lo), "=f"(hi) : "l"(v));
}
__device__ __forceinline__ void fma2(u64& acc, u64 a, u64 b) {
    asm("fma.rn.f32x2 %0, %1, %2, %0;" : "+l"(acc) : "l"(a), "l"(b));
}

// accumulate fp16 row fragment (uint2 = 4 halves) into float4
__device__ __forceinline__ void acc_h4(float4& acc, uint2 u) {
    __half2 a = *(__half2*)&u.x;
    __half2 b = *(__half2*)&u.y;
    float2 fa = __half22float2(a);
    float2 fb = __half22float2(b);
    acc.x += fa.x; acc.y += fa.y; acc.z += fb.x; acc.w += fb.y;
}

// ------------------------------------------------------------------
// CSR build
// ------------------------------------------------------------------
__global__ __launch_bounds__(256) void k_zero() {
    int i = blockIdx.x * 256 + threadIdx.x;
    if (i < NP) { g_pcnt[i] = 0; g_dcnt[i] = 0; }
}

__global__ __launch_bounds__(256) void k_count(const int* __restrict__ pdst,
                                               const int* __restrict__ dprot) {
    int e = blockIdx.x * 256 + threadIdx.x;
    if (e < EP) atomicAdd(&g_pcnt[__ldg(pdst + e)], 1);
    else if (e < EP + ED) atomicAdd(&g_dcnt[__ldg(dprot + (e - EP))], 1);
}

__global__ __launch_bounds__(256) void k_scan1() {
    __shared__ int sp[256], sd[256];
    int t = threadIdx.x;
    int i = blockIdx.x * 256 + t;
    int vp = (i < NP) ? g_pcnt[i] : 0;
    int vd = (i < NP) ? g_dcnt[i] : 0;
    sp[t] = vp; sd[t] = vd;
    __syncthreads();
#pragma unroll
    for (int off = 1; off < 256; off <<= 1) {
        int ap = 0, ad = 0;
        if (t >= off) { ap = sp[t - off]; ad = sd[t - off]; }
        __syncthreads();
        sp[t] += ap; sd[t] += ad;
        __syncthreads();
    }
    if (i < NP) { g_pstart[i] = sp[t] - vp; g_dstart[i] = sd[t] - vd; }
    if (t == 255) { g_pbsum[blockIdx.x] = sp[255]; g_dbsum[blockIdx.x] = sd[255]; }
}

__global__ __launch_bounds__(512) void k_scan2() {
    __shared__ int sp[512], sd[512];
    int t = threadIdx.x;
    int vp = (t < NB) ? g_pbsum[t] : 0;
    int vd = (t < NB) ? g_dbsum[t] : 0;
    sp[t] = vp; sd[t] = vd;
    __syncthreads();
#pragma unroll
    for (int off = 1; off < 512; off <<= 1) {
        int ap = 0, ad = 0;
        if (t >= off) { ap = sp[t - off]; ad = sd[t - off]; }
        __syncthreads();
        sp[t] += ap; sd[t] += ad;
        __syncthreads();
    }
    if (t < NB) { g_pboff[t] = sp[t] - vp; g_dboff[t] = sd[t] - vd; }
}

__global__ __launch_bounds__(256) void k_scan3() {
    int i = blockIdx.x * 256 + threadIdx.x;
    if (i < NP) {
        int ps = g_pstart[i] + g_pboff[blockIdx.x];
        int ds = g_dstart[i] + g_dboff[blockIdx.x];
        g_pstart[i] = ps; g_pcur[i] = ps;
        g_dstart[i] = ds; g_dcur[i] = ds;
        g_dinv[i] = rsqrtf((float)(g_pcnt[i] + 1));        // +1 self loop
        g_cinv[i] = 1.0f / fmaxf((float)g_dcnt[i], 1.0f);  // mean divisor
    }
    if (i == 0) { g_pstart[NP] = EP; g_dstart[NP] = ED; }
}

__global__ __launch_bounds__(256) void k_fill(const int* __restrict__ psrc,
                                              const int* __restrict__ pdst,
                                              const int* __restrict__ ddrug,
                                              const int* __restrict__ dprot) {
    int e = blockIdx.x * 256 + threadIdx.x;
    if (e < EP) {
        int c = __ldg(pdst + e);
        int pos = atomicAdd(&g_pcur[c], 1);
        g_plist[pos] = __ldg(psrc + e);
    } else if (e < EP + ED) {
        int ee = e - EP;
        int c = __ldg(dprot + ee);
        int pos = atomicAdd(&g_dcur[c], 1);
        g_dlist[pos] = __ldg(ddrug + ee);
    }
}

// ------------------------------------------------------------------
// Drug GEMM (FFMA2): g_msgs = fp16(x_drug @ W_td + b_td)
// ------------------------------------------------------------------
__global__ __launch_bounds__(256) void k_gemm_drug(
    const float* __restrict__ A, const float* __restrict__ B,
    const float* __restrict__ bias) {
    __shared__ float XsT[BK][BM + 4];
    __shared__ float Bs[BK][DD];
    int tid = threadIdx.x;
    int tx = tid & 15, ty = tid >> 4;
    int row0 = blockIdx.x * BM;

    u64 acc[4][4];
#pragma unroll
    for (int i = 0; i < 4; i++)
#pragma unroll
        for (int j = 0; j < 4; j++) acc[i][j] = 0ull;

    for (int k0 = 0; k0 < DD; k0 += BK) {
        {
            int r = tid >> 2;
            int kc = (tid & 3) * 4;
            float4 v = make_float4(0.f, 0.f, 0.f, 0.f);
            int gr = row0 + r;
            if (gr < ND) v = *(const float4*)(A + (size_t)gr * DD + k0 + kc);
            XsT[kc + 0][r] = v.x; XsT[kc + 1][r] = v.y;
            XsT[kc + 2][r] = v.z; XsT[kc + 3][r] = v.w;
        }
#pragma unroll
        for (int u = 0; u < 2; u++) {
            int idx = tid + u * 256;
            int k = idx >> 5, c4 = idx & 31;
            *(float4*)&Bs[k][c4 * 4] =
                *(const float4*)(B + (size_t)(k0 + k) * DD + c4 * 4);
        }
        __syncthreads();
#pragma unroll
        for (int k = 0; k < BK; k++) {
            float4 a = *(const float4*)&XsT[k][ty * 4];
            u64 pa[4] = {pk2(a.x, a.x), pk2(a.y, a.y), pk2(a.z, a.z), pk2(a.w, a.w)};
            ulonglong2 b0 = *(const ulonglong2*)&Bs[k][tx * 8];
            ulonglong2 b1 = *(const ulonglong2*)&Bs[k][tx * 8 + 4];
            u64 bp[4] = {b0.x, b0.y, b1.x, b1.y};
#pragma unroll
            for (int i = 0; i < 4; i++)
#pragma unroll
                for (int j = 0; j < 4; j++) fma2(acc[i][j], pa[i], bp[j]);
        }
        __syncthreads();
    }
#pragma unroll
    for (int i = 0; i < 4; i++) {
        int r = row0 + ty * 4 + i;
        if (r < ND) {
            __half2 hh[4];
#pragma unroll
            for (int j = 0; j < 4; j++) {
                float lo, hi;
                upk2(lo, hi, acc[i][j]);
                int c = tx * 8 + 2 * j;
                hh[j] = __floats2half2_rn(lo + __ldg(bias + c),
                                          hi + __ldg(bias + c + 1));
            }
            *(uint4*)(g_msgs + (size_t)r * DD + tx * 8) = *(uint4*)hh;
        }
    }
}

// ------------------------------------------------------------------
// Pre-GEMM (FFMA2, single A tile, dual B):
//   g_h1s = fp16( dinv .* (x @ W_gcn) )
//   g_h3  = x @ W_pr + b_pr + b_gcn + 1e-6   (fp32)
// ------------------------------------------------------------------
__global__ __launch_bounds__(256) void k_pre(
    const float* __restrict__ A,    // x_prot
    const float* __restrict__ Bg,   // W_gcn
    const float* __restrict__ Bx,   // W_pr
    const float* __restrict__ bg, const float* __restrict__ bx) {
    __shared__ float XsT[BK][BM + 4];
    __shared__ float Bs1[BK][DD], Bs2[BK][DD];
    int tid = threadIdx.x;
    int tx = tid & 15, ty = tid >> 4;
    int row0 = blockIdx.x * BM;

    u64 acc1[4][4], acc2[4][4];
#pragma unroll
    for (int i = 0; i < 4; i++)
#pragma unroll
        for (int j = 0; j < 4; j++) { acc1[i][j] = 0ull; acc2[i][j] = 0ull; }

    for (int k0 = 0; k0 < DD; k0 += BK) {
        {
            int r = tid >> 2;
            int kc = (tid & 3) * 4;
            int gr = row0 + r;
            float4 v = make_float4(0.f, 0.f, 0.f, 0.f);
            if (gr < NP) v = *(const float4*)(A + (size_t)gr * DD + k0 + kc);
            XsT[kc + 0][r] = v.x; XsT[kc + 1][r] = v.y;
            XsT[kc + 2][r] = v.z; XsT[kc + 3][r] = v.w;
        }
#pragma unroll
        for (int u = 0; u < 2; u++) {
            int idx = tid + u * 256;
            int k = idx >> 5, c4 = idx & 31;
            *(float4*)&Bs1[k][c4 * 4] =
                *(const float4*)(Bg + (size_t)(k0 + k) * DD + c4 * 4);
            *(float4*)&Bs2[k][c4 * 4] =
                *(const float4*)(Bx + (size_t)(k0 + k) * DD + c4 * 4);
        }
        __syncthreads();
#pragma unroll
        for (int k = 0; k < BK; k++) {
            float4 a = *(const float4*)&XsT[k][ty * 4];
            u64 pa[4] = {pk2(a.x, a.x), pk2(a.y, a.y), pk2(a.z, a.z), pk2(a.w, a.w)};
            ulonglong2 g0 = *(const ulonglong2*)&Bs1[k][tx * 8];
            ulonglong2 g1 = *(const ulonglong2*)&Bs1[k][tx * 8 + 4];
            ulonglong2 p0 = *(const ulonglong2*)&Bs2[k][tx * 8];
            ulonglong2 p1 = *(const ulonglong2*)&Bs2[k][tx * 8 + 4];
            u64 bgp[4] = {g0.x, g0.y, g1.x, g1.y};
            u64 bxp[4] = {p0.x, p0.y, p1.x, p1.y};
#pragma unroll
            for (int i = 0; i < 4; i++)
#pragma unroll
                for (int j = 0; j < 4; j++) {
                    fma2(acc1[i][j], pa[i], bgp[j]);
                    fma2(acc2[i][j], pa[i], bxp[j]);
                }
        }
        __syncthreads();
    }

    float bsum[8];
#pragma unroll
    for (int j = 0; j < 8; j++) {
        int c = tx * 8 + j;
        bsum[j] = __ldg(bg + c) + __ldg(bx + c) + 1e-6f;
    }

#pragma unroll
    for (int i = 0; i < 4; i++) {
        int r = row0 + ty * 4 + i;
        if (r < NP) {
            float dv = __ldg(g_dinv + r);
            __half2 hh[4];
#pragma unroll
            for (int j = 0; j < 4; j++) {
                float lo, hi;
                upk2(lo, hi, acc1[i][j]);
                hh[j] = __floats2half2_rn(lo * dv, hi * dv);
            }
            *(uint4*)(g_h1s + (size_t)r * DD + tx * 8) = *(uint4*)hh;

            float l0, h0, l1, h1, l2, h2, l3, h3v;
            upk2(l0, h0, acc2[i][0]); upk2(l1, h1, acc2[i][1]);
            upk2(l2, h2, acc2[i][2]); upk2(l3, h3v, acc2[i][3]);
            float4 h3a = make_float4(l0 + bsum[0], h0 + bsum[1],
                                     l1 + bsum[2], h1 + bsum[3]);
            float4 h3b = make_float4(l2 + bsum[4], h2 + bsum[5],
                                     l3 + bsum[6], h3v + bsum[7]);
            *(float4*)(g_h3 + (size_t)r * DD + tx * 8)     = h3a;
            *(float4*)(g_h3 + (size_t)r * DD + tx * 8 + 4) = h3b;
        }
    }
}

// ------------------------------------------------------------------
// Fused gather + LayerNorm: one warp per protein row.
// fp16 payloads (8 B / lane / edge), fp32 accumulation.
// ------------------------------------------------------------------
__global__ __launch_bounds__(256) void k_gather_ln(float* __restrict__ out) {
    int c = blockIdx.x * 8 + (threadIdx.x >> 5);
    if (c >= NP) return;
    int lane = threadIdx.x & 31;

    // PPI aggregate over pre-scaled h1s (self term included)
    float4 acc = make_float4(0.f, 0.f, 0.f, 0.f);
    acc_h4(acc, __ldg((const uint2*)(g_h1s + (size_t)c * DD) + lane));

    int i = __ldg(g_pstart + c), e = __ldg(g_pstart + c + 1);
    for (; i + 7 < e; i += 8) {
        int r[8];
        uint2 u[8];
#pragma unroll
        for (int t = 0; t < 8; t++) r[t] = __ldg(g_plist + i + t);
#pragma unroll
        for (int t = 0; t < 8; t++)
            u[t] = __ldg((const uint2*)(g_h1s + (size_t)r[t] * DD) + lane);
#pragma unroll
        for (int t = 0; t < 8; t++) acc_h4(acc, u[t]);
    }
    for (; i < e; i++) {
        int r0 = __ldg(g_plist + i);
        acc_h4(acc, __ldg((const uint2*)(g_h1s + (size_t)r0 * DD) + lane));
    }

    // DTI aggregate
    float4 accB = make_float4(0.f, 0.f, 0.f, 0.f);
    i = __ldg(g_dstart + c); e = __ldg(g_dstart + c + 1);
    for (; i + 3 < e; i += 4) {
        int d[4];
        uint2 u[4];
#pragma unroll
        for (int t = 0; t < 4; t++) d[t] = __ldg(g_dlist + i + t);
#pragma unroll
        for (int t = 0; t < 4; t++)
            u[t] = __ldg((const uint2*)(g_msgs + (size_t)d[t] * DD) + lane);
#pragma unroll
        for (int t = 0; t < 4; t++) acc_h4(accB, u[t]);
    }
    for (; i < e; i++) {
        int d0 = __ldg(g_dlist + i);
        acc_h4(accB, __ldg((const uint2*)(g_msgs + (size_t)d0 * DD) + lane));
    }

    float dc = __ldg(g_dinv + c);
    float ci = __ldg(g_cinv + c);
    float4 h3 = __ldg((const float4*)(g_h3 + (size_t)c * DD) + lane);
    float4 y;
    y.x = dc * acc.x + ci * accB.x + h3.x;
    y.y = dc * acc.y + ci * accB.y + h3.y;
    y.z = dc * acc.z + ci * accB.z + h3.z;
    y.w = dc * acc.w + ci * accB.w + h3.w;

    // LayerNorm over the 32-lane row (lane owns 4 consecutive cols)
    float s = (y.x + y.y) + (y.z + y.w);
#pragma unroll
    for (int o = 16; o > 0; o >>= 1) s += __shfl_xor_sync(0xffffffffu, s, o);
    float mu = s * (1.0f / DD);
    float dx = y.x - mu, dy = y.y - mu, dz = y.z - mu, dw = y.w - mu;
    float q = (dx * dx + dy * dy) + (dz * dz + dw * dw);
#pragma unroll
    for (int o = 16; o > 0; o >>= 1) q += __shfl_xor_sync(0xffffffffu, q, o);
    float inv = rsqrtf(q * (1.0f / DD) + 1e-5f);
    float4 o4 = make_float4(dx * inv, dy * inv, dz * inv, dw * inv);
    ((float4*)(out + (size_t)c * DD))[lane] = o4;
}

// ------------------------------------------------------------------
extern "C" void kernel_launch(void* const* d_in, const int* in_sizes, int n_in,
                              void* d_out, int out_size) {
    const float* x_prot = (const float*)d_in[0];
    const float* x_drug = (const float*)d_in[1];
    const float* W_gcn  = (const float*)d_in[2];
    const float* b_gcn  = (const float*)d_in[3];
    const float* W_td   = (const float*)d_in[4];
    const float* b_td   = (const float*)d_in[5];
    const float* W_pr   = (const float*)d_in[6];
    const float* b_pr   = (const float*)d_in[7];
    const int*   ppi    = (const int*)d_in[8];   // [2, EP]: src = ppi, dst = ppi+EP
    const int*   dti_d  = (const int*)d_in[9];
    const int*   dti_p  = (const int*)d_in[10];
    float* out = (float*)d_out;

    k_zero<<<NB, 256>>>();
    k_count<<<(EP + ED + 255) / 256, 256>>>(ppi + EP, dti_p);
    k_scan1<<<NB, 256>>>();
    k_scan2<<<1, 512>>>();
    k_scan3<<<NB, 256>>>();
    k_fill<<<(EP + ED + 255) / 256, 256>>>(ppi, ppi + EP, dti_d, dti_p);
    k_gemm_drug<<<(ND + BM - 1) / BM, 256>>>(x_drug, W_td, b_td);
    k_pre<<<(NP + BM - 1) / BM, 256>>>(x_prot, W_gcn, W_pr, b_gcn, b_pr);
    k_gather_ln<<<(NP + 7) / 8, 256>>>(out);
}